// round 9
// baseline (speedup 1.0000x reference)
#include <cuda_runtime.h>
#include <cuda_bf16.h>

// GRU scan: B=2048 sequences, T=2048 steps, D=3 input, H=32 hidden.
// out[b, t] = h[0] after step t.
//
// R9: back to ONE batch per warp (2048 warps, 3.46/SMSP) for latency hiding,
// with the register pressure that killed R5 removed by construction:
//  - k-pair f32x2 packing: matvec = 48 fma.rn.f32x2 (+3 folds), weights are
//    pairs of adjacent k -> NO duplication.
//  - r/z gate weights in regs (32 u64 = 64 regs); a-gate weight rows live in
//    a CTA-shared table (identical across warps), read as conflict-free
//    lane-strided LDS.128 (8/step). Total demand ~105 regs < 128 -> occ 4,
//    single wave (512 CTAs <= 592 slots), no spills.
//  - EX2/RCP activations (tanh.approx regressed on sm_103a: fma-pipe polyfill).

#define T_DIM 2048
#define B_DIM 2048

typedef unsigned long long u64;

__device__ __forceinline__ u64 fma2(u64 a, u64 b, u64 c) {
    u64 d;
    asm("fma.rn.f32x2 %0, %1, %2, %3;" : "=l"(d) : "l"(a), "l"(b), "l"(c));
    return d;
}

__device__ __forceinline__ float foldadd(u64 p) {
    float lo, hi;
    asm("mov.b64 {%0, %1}, %2;" : "=f"(lo), "=f"(hi) : "l"(p));
    return lo + hi;
}

__device__ __forceinline__ float sigm_f(float x) {
    return __fdividef(1.0f, 1.0f + __expf(-x));
}

__device__ __forceinline__ float tanh_f(float x) {
    return 1.0f - __fdividef(2.0f, __expf(2.0f * x) + 1.0f);
}

__global__ void __launch_bounds__(128, 4)
gru_scan_kernel(const float* __restrict__ inp,      // [B, T, 3]
                const float* __restrict__ wih,      // [96, 3]
                const float* __restrict__ whh,      // [96, 32]
                const float* __restrict__ bias,     // [96]
                const float* __restrict__ bias_n,   // [32]
                float* __restrict__ out)            // [B, T]
{
    const int lane = threadIdx.x & 31;
    const int warp = threadIdx.x >> 5;
    const int b    = blockIdx.x * 4 + warp;

    // per-warp double-buffered h slab (floats; read back as 16B pairs)
    __shared__ __align__(16) float hbuf[4][2][32];
    // a-gate weight table, shared by all 4 warps: wa_s[i][lane] holds
    // ((wa[4i],wa[4i+1]),(wa[4i+2],wa[4i+3])) for hidden unit `lane`.
    __shared__ __align__(16) ulonglong2 wa_s[8][32];

    if (warp == 0) {
        const u64* arow =
            reinterpret_cast<const u64*>(whh + (size_t)(64 + lane) * 32);
#pragma unroll
        for (int i = 0; i < 8; ++i) {
            ulonglong2 v;
            v.x = arow[2 * i];
            v.y = arow[2 * i + 1];
            wa_s[i][lane] = v;
        }
    }

    // --- r/z gate weights for this lane as packed k-pairs (64 regs) ---
    u64 wr[16], wz[16];
    {
        const u64* r0 = reinterpret_cast<const u64*>(whh + (size_t)(lane) * 32);
        const u64* r1 = reinterpret_cast<const u64*>(whh + (size_t)(32 + lane) * 32);
#pragma unroll
        for (int i = 0; i < 16; ++i) { wr[i] = r0[i]; wz[i] = r1[i]; }
    }
    const float wir0 = wih[lane * 3 + 0], wir1 = wih[lane * 3 + 1], wir2 = wih[lane * 3 + 2];
    const float wiz0 = wih[(32 + lane) * 3 + 0], wiz1 = wih[(32 + lane) * 3 + 1], wiz2 = wih[(32 + lane) * 3 + 2];
    const float wia0 = wih[(64 + lane) * 3 + 0], wia1 = wih[(64 + lane) * 3 + 1], wia2 = wih[(64 + lane) * 3 + 2];
    const float bir = bias[lane], biz = bias[32 + lane];
    const float bia = bias[64 + lane] + bias_n[lane];   // bias_n folded

    const float* xp = inp + (size_t)b * T_DIM * 3;
    float*       op = out + (size_t)b * T_DIM;

    float h = 0.0f;
    float x0 = __ldg(xp + 0), x1 = __ldg(xp + 1), x2 = __ldg(xp + 2);

    __syncthreads();   // wa_s ready

    for (int t = 0; t < T_DIM; ++t) {
        // input gates for current x; prefetch next x (clamped, branch-free)
        float ir = fmaf(wir2, x2, fmaf(wir1, x1, fmaf(wir0, x0, bir)));
        float iz = fmaf(wiz2, x2, fmaf(wiz1, x1, fmaf(wiz0, x0, biz)));
        float ia = fmaf(wia2, x2, fmaf(wia1, x1, fmaf(wia0, x0, bia)));
        {
            int tn = (t + 1 < T_DIM) ? (t + 1) : t;
            const float* nx = xp + (size_t)tn * 3;
            x0 = __ldg(nx + 0);
            x1 = __ldg(nx + 1);
            x2 = __ldg(nx + 2);
        }

        // publish h_j; double-buffered slot => one syncwarp per step
        const int slot = t & 1;
        hbuf[warp][slot][lane] = h;
        __syncwarp();

        u64 ar = 0ull, az = 0ull, aa = 0ull;
        const ulonglong2* hp =
            reinterpret_cast<const ulonglong2*>(&hbuf[warp][slot][0]);
#pragma unroll
        for (int i = 0; i < 8; ++i) {
            ulonglong2 hv = hp[i];          // broadcast: h[4i..4i+3] as 2 pairs
            ulonglong2 wv = wa_s[i][lane];  // lane-strided, conflict-free
            ar = fma2(wr[2 * i],     hv.x, ar);
            az = fma2(wz[2 * i],     hv.x, az);
            aa = fma2(wv.x,          hv.x, aa);
            ar = fma2(wr[2 * i + 1], hv.y, ar);
            az = fma2(wz[2 * i + 1], hv.y, az);
            aa = fma2(wv.y,          hv.y, aa);
        }
        float hr = foldadd(ar);
        float hz = foldadd(az);
        float ha = foldadd(aa);

        float r = sigm_f(ir + hr);
        float z = sigm_f(iz + hz);
        float n = tanh_f(fmaf(r, ha, ia));
        h = fmaf(z, h - n, n);              // (1-z)*n + z*h

        if (lane == 0) op[t] = h;
    }
}

extern "C" void kernel_launch(void* const* d_in, const int* in_sizes, int n_in,
                              void* d_out, int out_size) {
    const float* inp    = (const float*)d_in[0];
    const float* wih    = (const float*)d_in[1];
    const float* whh    = (const float*)d_in[2];
    const float* bias   = (const float*)d_in[3];
    const float* bias_n = (const float*)d_in[4];
    float* out = (float*)d_out;

    // 1 batch per warp, 4 warps per CTA -> 512 CTAs, 2048 warps, single wave.
    gru_scan_kernel<<<B_DIM / 4, 128>>>(inp, wih, whh, bias, bias_n, out);
}